// round 16
// baseline (speedup 1.0000x reference)
#include <cuda_runtime.h>
#include <cuda_fp16.h>
#include <cstdint>

#define TEMPERATURE 0.07f
constexpr int BSZ  = 256;
constexpr int MTOK = 128;
constexpr int DDIM = 768;

constexpr int KC     = 64;                 // K elements per smem stage (fp16)
constexpr int NCHUNK = DDIM / KC;          // 12
constexpr int PB     = 144;                // smem row pitch bytes (128 data + 16 pad)
constexpr int TILE_B = 128 * PB;           // 18432 bytes per tile
constexpr int STAGE_B = 2 * TILE_B;        // A, B
constexpr int SMEM_TOTAL = 2 * STAGE_B;    // 73728, double buffered -> occ 2

// Scratch device globals (no allocation allowed anywhere)
__device__ float g_S [BSZ * BSZ];          // max-sim, row-major
__device__ float g_ST[BSZ * BSZ];          // transposed copy (coalesced cols)
__device__ unsigned g_done;                // zero-init; tail CTA resets each replay

// ---------------------------------------------------------------------------
__device__ __forceinline__ uint32_t smem_u32(const void* p) {
    uint32_t a;
    asm("{ .reg .u64 t; cvta.to.shared.u64 t, %1; cvt.u32.u64 %0, t; }"
        : "=r"(a) : "l"(p));
    return a;
}
__device__ __forceinline__ void ldsm_x4(uint32_t* r, uint32_t addr) {
    asm volatile("ldmatrix.sync.aligned.m8n8.x4.shared.b16 {%0,%1,%2,%3}, [%4];"
                 : "=r"(r[0]), "=r"(r[1]), "=r"(r[2]), "=r"(r[3]) : "r"(addr));
}
__device__ __forceinline__ void mma_fp16(float* d, const uint32_t* a,
                                         const uint32_t* b) {
    asm volatile(
        "mma.sync.aligned.m16n8k16.row.col.f32.f16.f16.f32 "
        "{%0,%1,%2,%3}, {%4,%5,%6,%7}, {%8,%9}, {%0,%1,%2,%3};"
        : "+f"(d[0]), "+f"(d[1]), "+f"(d[2]), "+f"(d[3])
        : "r"(a[0]), "r"(a[1]), "r"(a[2]), "r"(a[3]), "r"(b[0]), "r"(b[1]));
}

// ---------------------------------------------------------------------------
// One kernel: 512 GEMM CTAs (grid y < 256) + 1 LSE tail CTA (y == 256).
// The branch is taken at kernel entry, so the two code paths are disjoint and
// the GEMM path's register allocation is unaffected by the tail code.
//
// GEMM path (identical to R14/R15): single-product fp16 mma.sync + fused max
// over m. 8 warps (4M x 2N), warp tile 32x64, occ 2. A and B loaded fp32 and
// converted in-kernel; A reuses br[] after sts(B) frees it.
//
// Tail path: spins until all 512 GEMM CTAs arrive (release/acquire via
// __threadfence + atomic), then does warp-per-row LSE and the deterministic
// fixed-order final sum in this single CTA, and resets g_done.
// ---------------------------------------------------------------------------
__global__ __launch_bounds__(256, 2)
void gemm_max_lse(const float* __restrict__ V, const float* __restrict__ T,
                  float* __restrict__ out) {
    extern __shared__ char smem[];
    const int tid  = threadIdx.x;
    const int lane = tid & 31;
    const int wid  = tid >> 5;

    // ===================== LSE tail CTA =====================
    if (blockIdx.y == BSZ) {
        if (blockIdx.x != 0) return;
        __shared__ float sm_part[BSZ];
        __shared__ float bsum[8];

        if (tid == 0) { while (atomicAdd(&g_done, 0u) < 512u) {} }
        __syncthreads();
        __threadfence();   // acquire (gpu scope -> L1D invalidate)

        const float INV = 1.0f / TEMPERATURE;
#pragma unroll 1
        for (int r = 0; r < 32; r++) {
            const int i = r * 8 + wid;
            const float4 r0 = __ldcg((const float4*)(g_S  + (size_t)i * BSZ + 4 * lane));
            const float4 r1 = __ldcg((const float4*)(g_S  + (size_t)i * BSZ + 128 + 4 * lane));
            const float4 c0 = __ldcg((const float4*)(g_ST + (size_t)i * BSZ + 4 * lane));
            const float4 c1 = __ldcg((const float4*)(g_ST + (size_t)i * BSZ + 128 + 4 * lane));

            float rm = fmaxf(fmaxf(fmaxf(r0.x, r0.y), fmaxf(r0.z, r0.w)),
                             fmaxf(fmaxf(r1.x, r1.y), fmaxf(r1.z, r1.w)));
            float cm = fmaxf(fmaxf(fmaxf(c0.x, c0.y), fmaxf(c0.z, c0.w)),
                             fmaxf(fmaxf(c1.x, c1.y), fmaxf(c1.z, c1.w)));
#pragma unroll
            for (int s = 16; s >= 1; s >>= 1) {
                rm = fmaxf(rm, __shfl_xor_sync(0xffffffffu, rm, s));
                cm = fmaxf(cm, __shfl_xor_sync(0xffffffffu, cm, s));
            }
            float rs = __expf((r0.x - rm) * INV) + __expf((r0.y - rm) * INV)
                     + __expf((r0.z - rm) * INV) + __expf((r0.w - rm) * INV)
                     + __expf((r1.x - rm) * INV) + __expf((r1.y - rm) * INV)
                     + __expf((r1.z - rm) * INV) + __expf((r1.w - rm) * INV);
            float cs = __expf((c0.x - cm) * INV) + __expf((c0.y - cm) * INV)
                     + __expf((c0.z - cm) * INV) + __expf((c0.w - cm) * INV)
                     + __expf((c1.x - cm) * INV) + __expf((c1.y - cm) * INV)
                     + __expf((c1.z - cm) * INV) + __expf((c1.w - cm) * INV);
#pragma unroll
            for (int s = 16; s >= 1; s >>= 1) {
                rs += __shfl_xor_sync(0xffffffffu, rs, s);
                cs += __shfl_xor_sync(0xffffffffu, cs, s);
            }
            if (lane == 0) {
                const float diag = __ldcg(g_S + (size_t)i * BSZ + i) * INV;
                sm_part[i] = (rm * INV + logf(rs) - diag)
                           + (cm * INV + logf(cs) - diag);
            }
        }
        __syncthreads();

        // Deterministic fixed-order final sum (single CTA).
        float v = sm_part[tid];
#pragma unroll
        for (int s = 16; s >= 1; s >>= 1) v += __shfl_xor_sync(0xffffffffu, v, s);
        if (lane == 0) bsum[wid] = v;
        __syncthreads();
        if (tid == 0) {
            float tot = 0.0f;
#pragma unroll
            for (int k = 0; k < 8; k++) tot += bsum[k];
            out[0] = tot * (1.0f / (2.0f * (float)BSZ));
            g_done = 0u;                // reset for next graph replay
            __threadfence();
        }
        return;
    }

    // ===================== GEMM path (R14/R15, unchanged) =====================
    const uint32_t sbase = smem_u32(smem);
    const int warp_m = wid & 3;
    const int warp_n = wid >> 2;

    const int i0 = blockIdx.x * 128;
    const int j  = blockIdx.y;
    const float* __restrict__ Tj = T + (size_t)j * MTOK * DDIM;
    const float* __restrict__ Vi = V + (size_t)i0 * DDIM;

    float acc[2][8][4];
#pragma unroll
    for (int mt = 0; mt < 2; mt++)
#pragma unroll
        for (int nt = 0; nt < 8; nt++)
#pragma unroll
            for (int e = 0; e < 4; e++) acc[mt][nt][e] = 0.0f;

    const int q   = lane >> 3;
    const int idx = lane & 7;
    const uint32_t a_off = (uint32_t)((warp_m * 32 + ((q & 1) * 8 + idx)) * PB
                                      + (q >> 1) * 16);
    const uint32_t b_off = (uint32_t)((warp_n * 64 + ((q >> 1) * 8 + idx)) * PB
                                      + (q & 1) * 16);

    float4 br[8];   // shared prefetch buffer: B, then A (disjoint live ranges)

    auto ldg_tile = [&](const float* __restrict__ src, int k0) {
#pragma unroll
        for (int p = 0; p < 8; p++) {
            const int u = p * 256 + tid;
            br[p] = *(const float4*)(src + (size_t)(u >> 4) * DDIM + k0 + (u & 15) * 4);
        }
    };
    auto sts_tile = [&](char* stage, int base) {
        char* sD = stage + base;
#pragma unroll
        for (int p = 0; p < 8; p++) {
            const int u   = p * 256 + tid;
            const int row = u >> 4;
            const int kq  = (u & 15) * 4;
            const float4 b = br[p];
            __half2 h01 = __floats2half2_rn(b.x, b.y);
            __half2 h23 = __floats2half2_rn(b.z, b.w);
            *(uint2*)(sD + row * PB + kq * 2) =
                make_uint2(*reinterpret_cast<unsigned*>(&h01),
                           *reinterpret_cast<unsigned*>(&h23));
        }
    };
    auto compute_step = [&](uint32_t sstage, int ks) {
        uint32_t ah[2][4], bh[4][4];
#pragma unroll
        for (int mt = 0; mt < 2; mt++)
            ldsm_x4(ah[mt], sstage + a_off + mt * 16 * PB + ks * 32);
#pragma unroll
        for (int np = 0; np < 4; np++)
            ldsm_x4(bh[np], sstage + TILE_B + b_off + np * 16 * PB + ks * 32);
#pragma unroll
        for (int np = 0; np < 4; np++)
#pragma unroll
            for (int mt = 0; mt < 2; mt++) {
                mma_fp16(acc[mt][2 * np],     ah[mt], bh[np]);
                mma_fp16(acc[mt][2 * np + 1], ah[mt], bh[np] + 2);
            }
    };

    // Prologue: chunk 0 -> stage 0 (A then B, sequential br reuse).
    ldg_tile(Vi, 0);
    sts_tile(smem, 0);           // A tile
    ldg_tile(Tj, 0);
    sts_tile(smem, TILE_B);      // B tile
    __syncthreads();

    for (int c = 0; c < NCHUNK; c++) {
        const int s = c & 1;
        const bool has_next = (c + 1 < NCHUNK);
        const int  knext = (c + 1) * KC;
        char* other = smem + (1 - s) * STAGE_B;
        if (has_next) ldg_tile(Tj, knext);                 // B LDG latency ->
        const uint32_t sstage = sbase + s * STAGE_B;       // hidden under MMAs
        compute_step(sstage, 0);
        compute_step(sstage, 1);
        compute_step(sstage, 2);
        if (has_next) {
            sts_tile(other, TILE_B);                       // B regs -> smem
            ldg_tile(Vi, knext);                           // A LDG (L2-hot)
        }
        compute_step(sstage, 3);
        if (has_next) sts_tile(other, 0);                  // A regs -> smem
        __syncthreads();
    }

    // Epilogue: max over the 128 m columns per i-row; write S and S^T.
    float* buf = (float*)smem;   // [128][2]
#pragma unroll
    for (int mt = 0; mt < 2; mt++) {
        float mlo = -3.402823466e+38f, mhi = -3.402823466e+38f;
#pragma unroll
        for (int nt = 0; nt < 8; nt++) {
            mlo = fmaxf(mlo, fmaxf(acc[mt][nt][0], acc[mt][nt][1]));
            mhi = fmaxf(mhi, fmaxf(acc[mt][nt][2], acc[mt][nt][3]));
        }
        mlo = fmaxf(mlo, __shfl_xor_sync(0xffffffffu, mlo, 1));
        mlo = fmaxf(mlo, __shfl_xor_sync(0xffffffffu, mlo, 2));
        mhi = fmaxf(mhi, __shfl_xor_sync(0xffffffffu, mhi, 1));
        mhi = fmaxf(mhi, __shfl_xor_sync(0xffffffffu, mhi, 2));
        if ((lane & 3) == 0) {
            const int row = warp_m * 32 + mt * 16 + (lane >> 2);
            buf[row * 2 + warp_n]       = mlo;
            buf[(row + 8) * 2 + warp_n] = mhi;
        }
    }
    __syncthreads();
    if (tid < 128) {
        const float v = fmaxf(buf[tid * 2], buf[tid * 2 + 1]);
        g_S [(size_t)(i0 + tid) * BSZ + j] = v;
        g_ST[(size_t)j * BSZ + (i0 + tid)] = v;   // coalesced
    }

    // Release: stores -> fence -> barrier -> one arrival per CTA.
    __threadfence();
    __syncthreads();
    if (tid == 0) atomicAdd(&g_done, 1u);
}

// ---------------------------------------------------------------------------
extern "C" void kernel_launch(void* const* d_in, const int* in_sizes, int n_in,
                              void* d_out, int out_size) {
    const float* V = (const float*)d_in[0];  // v_final [256, 768]
    const float* T = (const float*)d_in[1];  // T_fused [256, 128, 768]
    float* out = (float*)d_out;

    cudaFuncSetAttribute(gemm_max_lse, cudaFuncAttributeMaxDynamicSharedMemorySize,
                         SMEM_TOTAL);

    gemm_max_lse<<<dim3(2, BSZ + 1), 256, SMEM_TOTAL>>>(V, T, out);
}

// round 17
// speedup vs baseline: 1.4080x; 1.4080x over previous
#include <cuda_runtime.h>
#include <cuda_fp16.h>
#include <cstdint>

#define TEMPERATURE 0.07f
constexpr int BSZ  = 256;
constexpr int MTOK = 128;
constexpr int DDIM = 768;

constexpr int KC     = 64;                 // K elements per smem stage (fp16)
constexpr int NCHUNK = DDIM / KC;          // 12
constexpr int PB     = 144;                // smem row pitch bytes (128 data + 16 pad)
constexpr int TILE_B = 128 * PB;           // 18432 bytes per tile
constexpr int STAGE_B = 2 * TILE_B;        // A, B
constexpr int SMEM_TOTAL = 2 * STAGE_B;    // 73728, double buffered -> occ 2

// Scratch device globals (no allocation allowed anywhere)
__device__ float g_S [BSZ * BSZ];          // max-sim, row-major
__device__ float g_ST[BSZ * BSZ];          // transposed copy (coalesced cols)
__device__ float g_partial[BSZ];
__device__ unsigned g_count;               // zero-init; lse resets it each replay

// ---------------------------------------------------------------------------
__device__ __forceinline__ uint32_t smem_u32(const void* p) {
    uint32_t a;
    asm("{ .reg .u64 t; cvta.to.shared.u64 t, %1; cvt.u32.u64 %0, t; }"
        : "=r"(a) : "l"(p));
    return a;
}
__device__ __forceinline__ void ldsm_x4(uint32_t* r, uint32_t addr) {
    asm volatile("ldmatrix.sync.aligned.m8n8.x4.shared.b16 {%0,%1,%2,%3}, [%4];"
                 : "=r"(r[0]), "=r"(r[1]), "=r"(r[2]), "=r"(r[3]) : "r"(addr));
}
__device__ __forceinline__ void mma_fp16(float* d, const uint32_t* a,
                                         const uint32_t* b) {
    asm volatile(
        "mma.sync.aligned.m16n8k16.row.col.f32.f16.f16.f32 "
        "{%0,%1,%2,%3}, {%4,%5,%6,%7}, {%8,%9}, {%0,%1,%2,%3};"
        : "+f"(d[0]), "+f"(d[1]), "+f"(d[2]), "+f"(d[3])
        : "r"(a[0]), "r"(a[1]), "r"(a[2]), "r"(a[3]), "r"(b[0]), "r"(b[1]));
}

// ---------------------------------------------------------------------------
// Kernel 1: single-product fp16 mma.sync GEMM + fused max over m.
// Grid (2, 256), 8 warps (4M x 2N), warp tile 32x64, occ 2.
// A and B loaded fp32 and converted in-kernel; in the main loop A reuses the
// br[] registers after sts(B) frees them. Prologue overlaps the A and B
// chunk-0 loads (br + prologue-scoped br2, whose live range ends before acc
// goes live -> loop register allocation untouched).
// ---------------------------------------------------------------------------
__global__ __launch_bounds__(256, 2)
void gemm_max_mma(const float* __restrict__ V, const float* __restrict__ T) {
    extern __shared__ char smem[];
    const uint32_t sbase = smem_u32(smem);
    const int tid  = threadIdx.x;
    const int lane = tid & 31;
    const int wid  = tid >> 5;
    const int warp_m = wid & 3;
    const int warp_n = wid >> 2;

    const int i0 = blockIdx.x * 128;
    const int j  = blockIdx.y;
    const float* __restrict__ Tj = T + (size_t)j * MTOK * DDIM;
    const float* __restrict__ Vi = V + (size_t)i0 * DDIM;

    // ldmatrix lane offsets (tile-relative, bytes)
    const int q   = lane >> 3;
    const int idx = lane & 7;
    const uint32_t a_off = (uint32_t)((warp_m * 32 + ((q & 1) * 8 + idx)) * PB
                                      + (q >> 1) * 16);
    const uint32_t b_off = (uint32_t)((warp_n * 64 + ((q >> 1) * 8 + idx)) * PB
                                      + (q & 1) * 16);

    float4 br[8];   // shared prefetch buffer: B, then A (disjoint live ranges)

    auto ldg_tile = [&](const float* __restrict__ src, int k0) {
#pragma unroll
        for (int p = 0; p < 8; p++) {
            const int u = p * 256 + tid;
            br[p] = *(const float4*)(src + (size_t)(u >> 4) * DDIM + k0 + (u & 15) * 4);
        }
    };
    auto sts_tile = [&](char* stage, int base) {
        char* sD = stage + base;
#pragma unroll
        for (int p = 0; p < 8; p++) {
            const int u   = p * 256 + tid;
            const int row = u >> 4;
            const int kq  = (u & 15) * 4;
            const float4 b = br[p];
            __half2 h01 = __floats2half2_rn(b.x, b.y);
            __half2 h23 = __floats2half2_rn(b.z, b.w);
            *(uint2*)(sD + row * PB + kq * 2) =
                make_uint2(*reinterpret_cast<unsigned*>(&h01),
                           *reinterpret_cast<unsigned*>(&h23));
        }
    };

    // ---- Prologue: chunk 0, A and B LDGs overlapped -----------------------
    {
        float4 br2[8];              // prologue-only; dead before acc init
#pragma unroll
        for (int p = 0; p < 8; p++) {
            const int u = p * 256 + tid;
            br[p]  = *(const float4*)(Vi + (size_t)(u >> 4) * DDIM + (u & 15) * 4);
            br2[p] = *(const float4*)(Tj + (size_t)(u >> 4) * DDIM + (u & 15) * 4);
        }
        sts_tile(smem, 0);          // A tile (from br)
#pragma unroll
        for (int p = 0; p < 8; p++) br[p] = br2[p];
        sts_tile(smem, TILE_B);     // B tile (from br2 via br)
    }
    __syncthreads();

    float acc[2][8][4];
#pragma unroll
    for (int mt = 0; mt < 2; mt++)
#pragma unroll
        for (int nt = 0; nt < 8; nt++)
#pragma unroll
            for (int e = 0; e < 4; e++) acc[mt][nt][e] = 0.0f;

    auto compute_step = [&](uint32_t sstage, int ks) {
        uint32_t ah[2][4], bh[4][4];
#pragma unroll
        for (int mt = 0; mt < 2; mt++)
            ldsm_x4(ah[mt], sstage + a_off + mt * 16 * PB + ks * 32);
#pragma unroll
        for (int np = 0; np < 4; np++)
            ldsm_x4(bh[np], sstage + TILE_B + b_off + np * 16 * PB + ks * 32);
#pragma unroll
        for (int np = 0; np < 4; np++)
#pragma unroll
            for (int mt = 0; mt < 2; mt++) {
                mma_fp16(acc[mt][2 * np],     ah[mt], bh[np]);
                mma_fp16(acc[mt][2 * np + 1], ah[mt], bh[np] + 2);
            }
    };

    for (int c = 0; c < NCHUNK; c++) {
        const int s = c & 1;
        const bool has_next = (c + 1 < NCHUNK);
        const int  knext = (c + 1) * KC;
        char* other = smem + (1 - s) * STAGE_B;
        if (has_next) ldg_tile(Tj, knext);                 // B LDG latency ->
        const uint32_t sstage = sbase + s * STAGE_B;       // hidden under MMAs
        compute_step(sstage, 0);
        compute_step(sstage, 1);
        compute_step(sstage, 2);
        if (has_next) {
            sts_tile(other, TILE_B);                       // B regs -> smem
            ldg_tile(Vi, knext);                           // A LDG (L2-hot)
        }
        compute_step(sstage, 3);
        if (has_next) sts_tile(other, 0);                  // A regs -> smem
        __syncthreads();
    }

    // Epilogue: max over the 128 m columns per i-row; write S and S^T.
    float* buf = (float*)smem;   // [128][2]
#pragma unroll
    for (int mt = 0; mt < 2; mt++) {
        float mlo = -3.402823466e+38f, mhi = -3.402823466e+38f;
#pragma unroll
        for (int nt = 0; nt < 8; nt++) {
            mlo = fmaxf(mlo, fmaxf(acc[mt][nt][0], acc[mt][nt][1]));
            mhi = fmaxf(mhi, fmaxf(acc[mt][nt][2], acc[mt][nt][3]));
        }
        mlo = fmaxf(mlo, __shfl_xor_sync(0xffffffffu, mlo, 1));
        mlo = fmaxf(mlo, __shfl_xor_sync(0xffffffffu, mlo, 2));
        mhi = fmaxf(mhi, __shfl_xor_sync(0xffffffffu, mhi, 1));
        mhi = fmaxf(mhi, __shfl_xor_sync(0xffffffffu, mhi, 2));
        if ((lane & 3) == 0) {
            const int row = warp_m * 32 + mt * 16 + (lane >> 2);
            buf[row * 2 + warp_n]       = mlo;
            buf[(row + 8) * 2 + warp_n] = mhi;
        }
    }
    __syncthreads();
    if (tid < 128) {
        const float v = fmaxf(buf[tid * 2], buf[tid * 2 + 1]);
        g_S [(size_t)(i0 + tid) * BSZ + j] = v;
        g_ST[(size_t)j * BSZ + (i0 + tid)] = v;   // coalesced
    }
}

// ---------------------------------------------------------------------------
// Kernel 2: warp-per-row LSE (no block barriers in the hot path).
// Grid 32 x 256 threads: warp w of block b owns index i = b*8 + w. Each lane
// reads 2 float4 from the S row and 2 from the ST row (fully coalesced),
// reduces max and exp-sum purely in shfl. Last block (threadfence-reduction)
// does the deterministic fixed-order final sum and resets the counter.
// ---------------------------------------------------------------------------
__global__ __launch_bounds__(256)
void lse_finalize_kernel(float* __restrict__ out) {
    __shared__ float bsum[8];
    __shared__ unsigned is_last;
    const int t    = threadIdx.x;
    const int lane = t & 31;
    const int w    = t >> 5;
    const int i    = blockIdx.x * 8 + w;
    const float INV = 1.0f / TEMPERATURE;

    const float4 r0 = *(const float4*)(g_S  + (size_t)i * BSZ + 4 * lane);
    const float4 r1 = *(const float4*)(g_S  + (size_t)i * BSZ + 128 + 4 * lane);
    const float4 c0 = *(const float4*)(g_ST + (size_t)i * BSZ + 4 * lane);
    const float4 c1 = *(const float4*)(g_ST + (size_t)i * BSZ + 128 + 4 * lane);

    float rm = fmaxf(fmaxf(fmaxf(r0.x, r0.y), fmaxf(r0.z, r0.w)),
                     fmaxf(fmaxf(r1.x, r1.y), fmaxf(r1.z, r1.w)));
    float cm = fmaxf(fmaxf(fmaxf(c0.x, c0.y), fmaxf(c0.z, c0.w)),
                     fmaxf(fmaxf(c1.x, c1.y), fmaxf(c1.z, c1.w)));
#pragma unroll
    for (int s = 16; s >= 1; s >>= 1) {
        rm = fmaxf(rm, __shfl_xor_sync(0xffffffffu, rm, s));
        cm = fmaxf(cm, __shfl_xor_sync(0xffffffffu, cm, s));
    }

    float rs = __expf((r0.x - rm) * INV) + __expf((r0.y - rm) * INV)
             + __expf((r0.z - rm) * INV) + __expf((r0.w - rm) * INV)
             + __expf((r1.x - rm) * INV) + __expf((r1.y - rm) * INV)
             + __expf((r1.z - rm) * INV) + __expf((r1.w - rm) * INV);
    float cs = __expf((c0.x - cm) * INV) + __expf((c0.y - cm) * INV)
             + __expf((c0.z - cm) * INV) + __expf((c0.w - cm) * INV)
             + __expf((c1.x - cm) * INV) + __expf((c1.y - cm) * INV)
             + __expf((c1.z - cm) * INV) + __expf((c1.w - cm) * INV);
#pragma unroll
    for (int s = 16; s >= 1; s >>= 1) {
        rs += __shfl_xor_sync(0xffffffffu, rs, s);
        cs += __shfl_xor_sync(0xffffffffu, cs, s);
    }

    if (lane == 0) {
        const float diag = g_S[(size_t)i * BSZ + i] * INV;
        g_partial[i] = (rm * INV + logf(rs) - diag)
                     + (cm * INV + logf(cs) - diag);
    }

    // ---- threadfence-reduction: last of 32 blocks does the final sum ------
    __threadfence();
    __syncthreads();
    if (t == 0) {
        unsigned done = atomicAdd(&g_count, 1u);
        is_last = (done == 31u) ? 1u : 0u;
    }
    __syncthreads();

    if (is_last) {
        __threadfence();                 // make all g_partial writes visible
        float v = g_partial[t];
#pragma unroll
        for (int s = 16; s >= 1; s >>= 1) v += __shfl_xor_sync(0xffffffffu, v, s);
        if (lane == 0) bsum[w] = v;
        __syncthreads();
        if (t == 0) {
            float tot = 0.0f;
#pragma unroll
            for (int k = 0; k < 8; k++) tot += bsum[k];
            out[0] = tot * (1.0f / (2.0f * (float)BSZ));
            g_count = 0u;               // reset for next graph replay
            __threadfence();
        }
    }
}

// ---------------------------------------------------------------------------
extern "C" void kernel_launch(void* const* d_in, const int* in_sizes, int n_in,
                              void* d_out, int out_size) {
    const float* V = (const float*)d_in[0];  // v_final [256, 768]
    const float* T = (const float*)d_in[1];  // T_fused [256, 128, 768]
    float* out = (float*)d_out;

    cudaFuncSetAttribute(gemm_max_mma, cudaFuncAttributeMaxDynamicSharedMemorySize,
                         SMEM_TOTAL);

    gemm_max_mma<<<dim3(2, BSZ), 256, SMEM_TOTAL>>>(V, T);
    lse_finalize_kernel<<<32, 256>>>(out);
}